// round 2
// baseline (speedup 1.0000x reference)
#include <cuda_runtime.h>

// Dilation1D: out[r] = max_{j=0..10} x[r-5+j] + h[j],  h[j] = -(j-5)^2/(4*scale)
// Exploit symmetry: out[r] = max(x[r], max_{d=1..5} max(x[r-d],x[r+d]) + h_d)

#define HALFK 5
#define VEC   8
#define BLOCK 256

__global__ __launch_bounds__(BLOCK) void dilate1d_kernel(
    const float* __restrict__ x,
    const float* __restrict__ scale_p,
    float* __restrict__ out,
    int n)
{
    int i = (blockIdx.x * BLOCK + threadIdx.x) * VEC;
    if (i >= n) return;

    const float s = *scale_p;
    const float c = -0.25f / s;
    const float h1 =  1.0f * c;
    const float h2 =  4.0f * c;
    const float h3 =  9.0f * c;
    const float h4 = 16.0f * c;
    const float h5 = 25.0f * c;

    const float NEG_INF = __int_as_float(0xff800000);

    // Window w[k] = x[i - 8 + k], k = 0..23 (covers x[i-5 .. i+12] needed,
    // rounded out to aligned float4 chunks).
    float w[24];

    if (i >= 8 && i + 16 <= n) {
        // Fast path: 6 aligned float4 loads (i is a multiple of 8 -> 32B aligned).
        const float4* p = reinterpret_cast<const float4*>(x + i - 8);
        #pragma unroll
        for (int q = 0; q < 6; q++) {
            float4 v = p[q];
            w[q * 4 + 0] = v.x;
            w[q * 4 + 1] = v.y;
            w[q * 4 + 2] = v.z;
            w[q * 4 + 3] = v.w;
        }
    } else {
        // Boundary path: scalar loads with -inf padding (matches reference).
        #pragma unroll
        for (int k = 0; k < 24; k++) {
            int idx = i - 8 + k;
            w[k] = (idx >= 0 && idx < n) ? x[idx] : NEG_INF;
        }
    }

    float o[VEC];
    #pragma unroll
    for (int v = 0; v < VEC; v++) {
        // center tap: h[5] = 0
        float r = w[v + 8];
        r = fmaxf(r, fmaxf(w[v + 7], w[v + 9])  + h1);
        r = fmaxf(r, fmaxf(w[v + 6], w[v + 10]) + h2);
        r = fmaxf(r, fmaxf(w[v + 5], w[v + 11]) + h3);
        r = fmaxf(r, fmaxf(w[v + 4], w[v + 12]) + h4);
        r = fmaxf(r, fmaxf(w[v + 3], w[v + 13]) + h5);
        o[v] = r;
    }

    if (i + VEC <= n) {
        float4* po = reinterpret_cast<float4*>(out + i);
        po[0] = make_float4(o[0], o[1], o[2], o[3]);
        po[1] = make_float4(o[4], o[5], o[6], o[7]);
    } else {
        #pragma unroll
        for (int v = 0; v < VEC; v++) {
            if (i + v < n) out[i + v] = o[v];
        }
    }
}

extern "C" void kernel_launch(void* const* d_in, const int* in_sizes, int n_in,
                              void* d_out, int out_size)
{
    const float* x       = (const float*)d_in[0];
    const float* scale_p = (const float*)d_in[1];
    float*       out     = (float*)d_out;
    int n = in_sizes[0];

    int threads = (n + VEC - 1) / VEC;
    int blocks  = (threads + BLOCK - 1) / BLOCK;
    dilate1d_kernel<<<blocks, BLOCK>>>(x, scale_p, out, n);
}